// round 10
// baseline (speedup 1.0000x reference)
#include <cuda_runtime.h>
#include <cuda_fp16.h>
#include <cstdint>

#define NB 16
#define NT 8192
#define NE 64
#define NC 128

// ---- smem layout: K and V row images [j][72 fp16] ----
#define STR  144
#define KOFF 0
#define VOFF 18432
#define SMEM_TOTAL 36864

#define QSCALE 0.18033688011112042f   // (1/8) * log2(e): softmax via ex2

__device__ __forceinline__ uint32_t smem_u32(const void* p) {
    uint32_t a;
    asm("{ .reg .u64 t; cvta.to.shared.u64 t, %1; cvt.u32.u64 %0, t; }" : "=r"(a) : "l"(p));
    return a;
}
__device__ __forceinline__ uint32_t pk2h(float a, float b) {
    __half2 t = __floats2half2_rn(a, b);
    return *(uint32_t*)&t;
}
__device__ __forceinline__ float2 unpk2h(uint32_t u) {
    __half2 t = *(__half2*)&u;
    return __half22float2(t);
}
__device__ __forceinline__ float ex2a(float x) {
    float r; asm("ex2.approx.f32 %0, %1;" : "=f"(r) : "f"(x)); return r;
}

#define MMAF16(d0,d1,d2,d3,a0,a1,a2,a3,b0,b1)                                \
    asm volatile("mma.sync.aligned.m16n8k16.row.col.f32.f16.f16.f32 "        \
                 "{%0,%1,%2,%3}, {%4,%5,%6,%7}, {%8,%9}, {%0,%1,%2,%3};"     \
                 : "+f"(d0), "+f"(d1), "+f"(d2), "+f"(d3)                    \
                 : "r"(a0), "r"(a1), "r"(a2), "r"(a3), "r"(b0), "r"(b1))

#define LDSM4(r0,r1,r2,r3,addr)                                              \
    asm volatile("ldmatrix.sync.aligned.m8n8.x4.shared.b16 {%0,%1,%2,%3}, [%4];" \
                 : "=r"(r0), "=r"(r1), "=r"(r2), "=r"(r3) : "r"(addr))

#define LDSM4T(r0,r1,r2,r3,addr)                                             \
    asm volatile("ldmatrix.sync.aligned.m8n8.x4.trans.shared.b16 {%0,%1,%2,%3}, [%4];" \
                 : "=r"(r0), "=r"(r1), "=r"(r2), "=r"(r3) : "r"(addr))

// ---------------- consumer: one warp, 16 rows, Np = 16G columns ----------------
template<int G>
__device__ __forceinline__ void warp_work(uint32_t smb, int R, int lane, int i0,
                                          const uint32_t qh[4][4],
                                          float* __restrict__ OutB, float* __restrict__ AB)
{
    const int g  = lane >> 2;
    const int tg = lane & 3;
    const int nv_lo = (i0 + R + g + 1) >> 6;
    const int nv_hi = (i0 + R + g + 8 + 1) >> 6;

    const uint32_t ka = smb + KOFF + (uint32_t)((lane & 7) * STR + (lane >> 3) * 16);
    const uint32_t va = smb + VOFF +
        (uint32_t)(((lane & 7) + ((lane >> 3) & 1) * 8) * STR + (lane >> 4) * 16);

    uint32_t p01[2 * G], p23[2 * G];
    float sum_lo = 0.0f, sum_hi = 0.0f;

    // ---- MMA1: n-tile pairs, 2 independent 4-chains; S in log2 domain ----
#pragma unroll
    for (int np = 0; np < G; ++np) {
        const int n0 = 2 * np;
        const uint32_t kan0 = ka + (uint32_t)(n0 * 8 * STR);
        const uint32_t kan1 = kan0 + 8 * STR;
        uint32_t k0[8], k1[8];
        LDSM4(k0[0], k0[1], k0[2], k0[3], kan0);
        LDSM4(k0[4], k0[5], k0[6], k0[7], kan0 + 64);
        LDSM4(k1[0], k1[1], k1[2], k1[3], kan1);
        LDSM4(k1[4], k1[5], k1[6], k1[7], kan1 + 64);

        float d0[4] = {0.f, 0.f, 0.f, 0.f};
        float d1[4] = {0.f, 0.f, 0.f, 0.f};
#pragma unroll
        for (int k = 0; k < 4; ++k) {
            MMAF16(d0[0], d0[1], d0[2], d0[3],
                   qh[k][0], qh[k][1], qh[k][2], qh[k][3], k0[2 * k], k0[2 * k + 1]);
            MMAF16(d1[0], d1[1], d1[2], d1[3],
                   qh[k][0], qh[k][1], qh[k][2], qh[k][3], k1[2 * k], k1[2 * k + 1]);
        }

#pragma unroll
        for (int h = 0; h < 2; ++h) {
            const float* d = h ? d1 : d0;
            const int n = n0 + h;
            const int j0 = 8 * n + 2 * tg;
            const float e0 = (j0     < nv_lo) ? ex2a(d[0]) : 0.0f;
            const float e1 = (j0 + 1 < nv_lo) ? ex2a(d[1]) : 0.0f;
            const float e2 = (j0     < nv_hi) ? ex2a(d[2]) : 0.0f;
            const float e3 = (j0 + 1 < nv_hi) ? ex2a(d[3]) : 0.0f;
            sum_lo += e0 + e1;
            sum_hi += e2 + e3;
            p01[n] = pk2h(e0, e1);
            p23[n] = pk2h(e2, e3);
        }
    }

    sum_lo += __shfl_xor_sync(0xffffffffu, sum_lo, 1);
    sum_lo += __shfl_xor_sync(0xffffffffu, sum_lo, 2);
    sum_hi += __shfl_xor_sync(0xffffffffu, sum_hi, 1);
    sum_hi += __shfl_xor_sync(0xffffffffu, sum_hi, 2);
    const float inv_lo = (nv_lo > 0) ? 1.0f / sum_lo : 0.0f;
    const float inv_hi = (nv_hi > 0) ? 1.0f / sum_hi : 0.0f;

    // ---- MMA2: Out = Ehat * V (A frags straight from exp regs) ----
    float o[8][4];
#pragma unroll
    for (int nt = 0; nt < 8; ++nt)
#pragma unroll
        for (int t = 0; t < 4; ++t) o[nt][t] = 0.0f;

#pragma unroll
    for (int kk = 0; kk < G; ++kk) {
        const uint32_t a0 = p01[2 * kk], a1 = p23[2 * kk];
        const uint32_t a2 = p01[2 * kk + 1], a3 = p23[2 * kk + 1];
        const uint32_t vak = va + (uint32_t)(kk * 16 * STR);

        uint32_t vh[16];
        LDSM4T(vh[0],  vh[1],  vh[2],  vh[3],  vak);
        LDSM4T(vh[4],  vh[5],  vh[6],  vh[7],  vak + 32);
        LDSM4T(vh[8],  vh[9],  vh[10], vh[11], vak + 64);
        LDSM4T(vh[12], vh[13], vh[14], vh[15], vak + 96);
#pragma unroll
        for (int nt = 0; nt < 8; ++nt) {
            const uint32_t b0 = vh[(nt >> 1) * 4 + (nt & 1) * 2];
            const uint32_t b1 = vh[(nt >> 1) * 4 + (nt & 1) * 2 + 1];
            MMAF16(o[nt][0], o[nt][1], o[nt][2], o[nt][3], a0, a1, a2, a3, b0, b1);
        }
    }

    // ---- write Out (normalized) ----
#pragma unroll
    for (int nt = 0; nt < 8; ++nt) {
        const int e = 8 * nt + 2 * tg;
        *(float2*)(OutB + (size_t)(R + g) * NE + e)     = make_float2(o[nt][0] * inv_lo, o[nt][1] * inv_lo);
        *(float2*)(OutB + (size_t)(R + g + 8) * NE + e) = make_float2(o[nt][2] * inv_hi, o[nt][3] * inv_hi);
    }
    // ---- write A (normalized) ----
#pragma unroll
    for (int n = 0; n < 2 * G; ++n) {
        const int j = 8 * n + 2 * tg;
        float2 v = unpk2h(p01[n]);
        *(float2*)(AB + (size_t)(R + g) * NC + j) = make_float2(v.x * inv_lo, v.y * inv_lo);
        v = unpk2h(p23[n]);
        *(float2*)(AB + (size_t)(R + g + 8) * NC + j) = make_float2(v.x * inv_hi, v.y * inv_hi);
    }
}

// ---------------- per-tile driver: load Q frags, run warp_work ----------------
template<int G>
__device__ __forceinline__ void do_tile(uint32_t smb, int R, int lane, int g, int tg,
                                        int i0, const float* __restrict__ Qg, int b,
                                        float* __restrict__ Outg, float* __restrict__ Ag)
{
    uint32_t qh[4][4];
    {
        const float* Qb = Qg + (size_t)(b * NT + i0) * NE;
        float2 qf[4][4];
#pragma unroll
        for (int k = 0; k < 4; ++k) {
            const float* q0 = Qb + (size_t)(R + g) * NE + 16 * k + 2 * tg;
            const float* q8 = q0 + 8 * NE;
            qf[k][0] = *(const float2*)q0;
            qf[k][1] = *(const float2*)q8;
            qf[k][2] = *(const float2*)(q0 + 8);
            qf[k][3] = *(const float2*)(q8 + 8);
        }
#pragma unroll
        for (int k = 0; k < 4; ++k)
#pragma unroll
            for (int t = 0; t < 4; ++t)
                qh[k][t] = pk2h(qf[k][t].x * QSCALE, qf[k][t].y * QSCALE);
    }
    float* OutB = Outg + (size_t)(b * NT + i0) * NE;
    float* AB   = Ag   + (size_t)(b * NT + i0) * NC;
    warp_work<G>(smb, R, lane, i0, qh, OutB, AB);
}

// ---------------- main kernel: one CTA = row-block pair (2q, 2q+1) ----------------
__global__ __launch_bounds__(256, 2)
void cba_pair(const float* __restrict__ Qg, const float* __restrict__ Kg,
              const float* __restrict__ Vg, float* __restrict__ Outg,
              float* __restrict__ Ag)
{
    extern __shared__ char sm[];
    const int tid  = (int)threadIdx.x;
    const int bid  = (int)blockIdx.x;
    const int lane = tid & 31;
    const int w    = tid >> 5;
    const int q    = 31 - (bid >> 4);      // heavy pairs first
    const int b    = bid & 15;
    const int c    = 4 * q + 4;            // columns needed by the hi tile
    const int G    = (c + 15) >> 4;        // identical for both tiles of the pair
    const int Np   = G << 4;
    const int i0lo = (2 * q) << 7;
    const int i0hi = (2 * q + 1) << 7;
    const int g    = lane >> 2;
    const int tg   = lane & 3;
    const int R    = w << 4;
    const uint32_t smb = smem_u32(sm);

    // ---- stage K/V: gathered rows [j][e] fp32 -> fp16 row images (inline) ----
    {
        const float* Kb = Kg + (size_t)b * NT * NE + (size_t)63 * NE;
        const float* Vb = Vg + (size_t)b * NT * NE + (size_t)63 * NE;
        for (int idx = tid; idx < c * 16; idx += 256) {
            const int j = idx >> 4, e4 = (idx & 15) << 2;
            const size_t goff = (size_t)j * 64 * NE + e4;
            const float4 k4 = *(const float4*)(Kb + goff);
            const float4 v4 = *(const float4*)(Vb + goff);
            char* dk = sm + KOFF + j * STR + e4 * 2;
            char* dv = sm + VOFF + j * STR + e4 * 2;
            *(uint2*)dk = make_uint2(pk2h(k4.x, k4.y), pk2h(k4.z, k4.w));
            *(uint2*)dv = make_uint2(pk2h(v4.x, v4.y), pk2h(v4.z, v4.w));
        }
        // zero pad rows [c, Np) (V pads are load-bearing for MMA2)
        for (int idx = tid; idx < (Np - c) * 16; idx += 256) {
            const int j = c + (idx >> 4), e4 = (idx & 15) << 2;
            *(uint2*)(sm + KOFF + j * STR + e4 * 2) = make_uint2(0u, 0u);
            *(uint2*)(sm + VOFF + j * STR + e4 * 2) = make_uint2(0u, 0u);
        }
    }

    // ---- zero A tail columns [Np, 128) for BOTH tiles (overlaps staging LDGs) ----
    if (G < 8) {
        const int t4 = (NC - Np) >> 2;
        float* Alo = Ag + (size_t)(b * NT + i0lo) * NC;
        for (int idx = tid; idx < 256 * t4; idx += 256) {
            const int row = idx / t4, cq = idx - row * t4;   // row 0..255 spans both tiles
            *(float4*)(Alo + (size_t)row * NC + Np + 4 * cq) =
                make_float4(0.f, 0.f, 0.f, 0.f);
        }
    }

    __syncthreads();

    switch (G) {
    case 1:
        do_tile<1>(smb, R, lane, g, tg, i0hi, Qg, b, Outg, Ag);
        do_tile<1>(smb, R, lane, g, tg, i0lo, Qg, b, Outg, Ag);
        break;
    case 2:
        do_tile<2>(smb, R, lane, g, tg, i0hi, Qg, b, Outg, Ag);
        do_tile<2>(smb, R, lane, g, tg, i0lo, Qg, b, Outg, Ag);
        break;
    case 3:
        do_tile<3>(smb, R, lane, g, tg, i0hi, Qg, b, Outg, Ag);
        do_tile<3>(smb, R, lane, g, tg, i0lo, Qg, b, Outg, Ag);
        break;
    case 4:
        do_tile<4>(smb, R, lane, g, tg, i0hi, Qg, b, Outg, Ag);
        do_tile<4>(smb, R, lane, g, tg, i0lo, Qg, b, Outg, Ag);
        break;
    case 5:
        do_tile<5>(smb, R, lane, g, tg, i0hi, Qg, b, Outg, Ag);
        do_tile<5>(smb, R, lane, g, tg, i0lo, Qg, b, Outg, Ag);
        break;
    case 6:
        do_tile<6>(smb, R, lane, g, tg, i0hi, Qg, b, Outg, Ag);
        do_tile<6>(smb, R, lane, g, tg, i0lo, Qg, b, Outg, Ag);
        break;
    case 7:
        do_tile<7>(smb, R, lane, g, tg, i0hi, Qg, b, Outg, Ag);
        do_tile<7>(smb, R, lane, g, tg, i0lo, Qg, b, Outg, Ag);
        break;
    default:
        do_tile<8>(smb, R, lane, g, tg, i0hi, Qg, b, Outg, Ag);
        do_tile<8>(smb, R, lane, g, tg, i0lo, Qg, b, Outg, Ag);
        break;
    }
}

extern "C" void kernel_launch(void* const* d_in, const int* in_sizes, int n_in,
                              void* d_out, int out_size)
{
    const float* Q = (const float*)d_in[0];
    const float* K = (const float*)d_in[1];
    const float* V = (const float*)d_in[2];
    float* Out = (float*)d_out;
    float* A   = Out + (size_t)NB * NT * NE;

    cudaFuncSetAttribute(cba_pair, cudaFuncAttributeMaxDynamicSharedMemorySize, SMEM_TOTAL);
    cba_pair<<<512, 256, SMEM_TOTAL>>>(Q, K, V, Out, A);
}

// round 11
// speedup vs baseline: 1.1727x; 1.1727x over previous
#include <cuda_runtime.h>
#include <cuda_fp16.h>
#include <cstdint>

#define NB 16
#define NT 8192
#define NE 64
#define NC 128

// ---- smem layout: K and V row images [j][72 fp16] ----
#define STR  144
#define KOFF 0
#define VOFF 18432
#define SMEM_TOTAL 36864

#define QSCALE 0.18033688011112042f   // (1/8) * log2(e): softmax via ex2

// ---- pre-converted gathered K/V scratch: exact 144B fp16 row images ----
__device__ __align__(16) char g_ksh[NB * 128 * STR];
__device__ __align__(16) char g_vsh[NB * 128 * STR];

__device__ __forceinline__ uint32_t smem_u32(const void* p) {
    uint32_t a;
    asm("{ .reg .u64 t; cvta.to.shared.u64 t, %1; cvt.u32.u64 %0, t; }" : "=r"(a) : "l"(p));
    return a;
}
__device__ __forceinline__ uint32_t pk2h(float a, float b) {
    __half2 t = __floats2half2_rn(a, b);
    return *(uint32_t*)&t;
}
__device__ __forceinline__ float2 unpk2h(uint32_t u) {
    __half2 t = *(__half2*)&u;
    return __half22float2(t);
}
__device__ __forceinline__ float ex2a(float x) {
    float r; asm("ex2.approx.f32 %0, %1;" : "=f"(r) : "f"(x)); return r;
}
#define CP16(dst, src)                                                       \
    asm volatile("cp.async.cg.shared.global [%0], [%1], 16;"                 \
                 :: "r"(dst), "l"(src) : "memory")

#define MMAF16(d0,d1,d2,d3,a0,a1,a2,a3,b0,b1)                                \
    asm volatile("mma.sync.aligned.m16n8k16.row.col.f32.f16.f16.f32 "        \
                 "{%0,%1,%2,%3}, {%4,%5,%6,%7}, {%8,%9}, {%0,%1,%2,%3};"     \
                 : "+f"(d0), "+f"(d1), "+f"(d2), "+f"(d3)                    \
                 : "r"(a0), "r"(a1), "r"(a2), "r"(a3), "r"(b0), "r"(b1))

#define LDSM4(r0,r1,r2,r3,addr)                                              \
    asm volatile("ldmatrix.sync.aligned.m8n8.x4.shared.b16 {%0,%1,%2,%3}, [%4];" \
                 : "=r"(r0), "=r"(r1), "=r"(r2), "=r"(r3) : "r"(addr))

#define LDSM4T(r0,r1,r2,r3,addr)                                             \
    asm volatile("ldmatrix.sync.aligned.m8n8.x4.trans.shared.b16 {%0,%1,%2,%3}, [%4];" \
                 : "=r"(r0), "=r"(r1), "=r"(r2), "=r"(r3) : "r"(addr))

// ---------------- pre-pass: convert gathered K/V to fp16 row images ----------------
__global__ __launch_bounds__(256)
void cba_prep(const float* __restrict__ Kg, const float* __restrict__ Vg)
{
    // 16384 units: each converts 8 e-values (32B fp32 -> 16B fp16) of one (b,j) row
    const int u  = (int)blockIdx.x * 256 + (int)threadIdx.x;
    const int b  = u >> 10;
    const int rem = u & 1023;
    const int j  = rem >> 3;
    const int e8 = (rem & 7) << 3;
    const size_t goff = ((size_t)(b * NT + 64 * j + 63)) * NE + e8;
    const size_t soff = (size_t)(b * 128 + j) * STR + e8 * 2;

    const float4 k0 = *(const float4*)(Kg + goff);
    const float4 k1 = *(const float4*)(Kg + goff + 4);
    *(uint4*)(g_ksh + soff) = make_uint4(pk2h(k0.x, k0.y), pk2h(k0.z, k0.w),
                                         pk2h(k1.x, k1.y), pk2h(k1.z, k1.w));
    const float4 v0 = *(const float4*)(Vg + goff);
    const float4 v1 = *(const float4*)(Vg + goff + 4);
    *(uint4*)(g_vsh + soff) = make_uint4(pk2h(v0.x, v0.y), pk2h(v0.z, v0.w),
                                         pk2h(v1.x, v1.y), pk2h(v1.z, v1.w));

    __threadfence();
    asm volatile("griddepcontrol.launch_dependents;");
}

// ---------------- consumer: one warp, 16 rows, Np = 16G columns ----------------
template<int G>
__device__ __forceinline__ void warp_work(uint32_t smb, int R, int lane, int i0,
                                          const uint32_t qh[4][4],
                                          float* __restrict__ OutB, float* __restrict__ AB)
{
    const int g  = lane >> 2;
    const int tg = lane & 3;
    const int nv_lo = (i0 + R + g + 1) >> 6;
    const int nv_hi = (i0 + R + g + 8 + 1) >> 6;

    const uint32_t ka = smb + KOFF + (uint32_t)((lane & 7) * STR + (lane >> 3) * 16);
    const uint32_t va = smb + VOFF +
        (uint32_t)(((lane & 7) + ((lane >> 3) & 1) * 8) * STR + (lane >> 4) * 16);

    uint32_t p01[2 * G], p23[2 * G];
    float sum_lo = 0.0f, sum_hi = 0.0f;

    // ---- MMA1: n-tile pairs, 2 independent 4-chains; S in log2 domain ----
#pragma unroll
    for (int np = 0; np < G; ++np) {
        const int n0 = 2 * np;
        const uint32_t kan0 = ka + (uint32_t)(n0 * 8 * STR);
        const uint32_t kan1 = kan0 + 8 * STR;
        uint32_t k0[8], k1[8];
        LDSM4(k0[0], k0[1], k0[2], k0[3], kan0);
        LDSM4(k0[4], k0[5], k0[6], k0[7], kan0 + 64);
        LDSM4(k1[0], k1[1], k1[2], k1[3], kan1);
        LDSM4(k1[4], k1[5], k1[6], k1[7], kan1 + 64);

        float d0[4] = {0.f, 0.f, 0.f, 0.f};
        float d1[4] = {0.f, 0.f, 0.f, 0.f};
#pragma unroll
        for (int k = 0; k < 4; ++k) {
            MMAF16(d0[0], d0[1], d0[2], d0[3],
                   qh[k][0], qh[k][1], qh[k][2], qh[k][3], k0[2 * k], k0[2 * k + 1]);
            MMAF16(d1[0], d1[1], d1[2], d1[3],
                   qh[k][0], qh[k][1], qh[k][2], qh[k][3], k1[2 * k], k1[2 * k + 1]);
        }

#pragma unroll
        for (int h = 0; h < 2; ++h) {
            const float* d = h ? d1 : d0;
            const int n = n0 + h;
            const int j0 = 8 * n + 2 * tg;
            const float e0 = (j0     < nv_lo) ? ex2a(d[0]) : 0.0f;
            const float e1 = (j0 + 1 < nv_lo) ? ex2a(d[1]) : 0.0f;
            const float e2 = (j0     < nv_hi) ? ex2a(d[2]) : 0.0f;
            const float e3 = (j0 + 1 < nv_hi) ? ex2a(d[3]) : 0.0f;
            sum_lo += e0 + e1;
            sum_hi += e2 + e3;
            p01[n] = pk2h(e0, e1);
            p23[n] = pk2h(e2, e3);
        }
    }

    sum_lo += __shfl_xor_sync(0xffffffffu, sum_lo, 1);
    sum_lo += __shfl_xor_sync(0xffffffffu, sum_lo, 2);
    sum_hi += __shfl_xor_sync(0xffffffffu, sum_hi, 1);
    sum_hi += __shfl_xor_sync(0xffffffffu, sum_hi, 2);
    const float inv_lo = (nv_lo > 0) ? 1.0f / sum_lo : 0.0f;
    const float inv_hi = (nv_hi > 0) ? 1.0f / sum_hi : 0.0f;

    // ---- MMA2: Out = Ehat * V (A frags straight from exp regs) ----
    float o[8][4];
#pragma unroll
    for (int nt = 0; nt < 8; ++nt)
#pragma unroll
        for (int t = 0; t < 4; ++t) o[nt][t] = 0.0f;

#pragma unroll
    for (int kk = 0; kk < G; ++kk) {
        const uint32_t a0 = p01[2 * kk], a1 = p23[2 * kk];
        const uint32_t a2 = p01[2 * kk + 1], a3 = p23[2 * kk + 1];
        const uint32_t vak = va + (uint32_t)(kk * 16 * STR);

        uint32_t vh[16];
        LDSM4T(vh[0],  vh[1],  vh[2],  vh[3],  vak);
        LDSM4T(vh[4],  vh[5],  vh[6],  vh[7],  vak + 32);
        LDSM4T(vh[8],  vh[9],  vh[10], vh[11], vak + 64);
        LDSM4T(vh[12], vh[13], vh[14], vh[15], vak + 96);
#pragma unroll
        for (int nt = 0; nt < 8; ++nt) {
            const uint32_t b0 = vh[(nt >> 1) * 4 + (nt & 1) * 2];
            const uint32_t b1 = vh[(nt >> 1) * 4 + (nt & 1) * 2 + 1];
            MMAF16(o[nt][0], o[nt][1], o[nt][2], o[nt][3], a0, a1, a2, a3, b0, b1);
        }
    }

    // ---- write Out (normalized) ----
#pragma unroll
    for (int nt = 0; nt < 8; ++nt) {
        const int e = 8 * nt + 2 * tg;
        *(float2*)(OutB + (size_t)(R + g) * NE + e)     = make_float2(o[nt][0] * inv_lo, o[nt][1] * inv_lo);
        *(float2*)(OutB + (size_t)(R + g + 8) * NE + e) = make_float2(o[nt][2] * inv_hi, o[nt][3] * inv_hi);
    }
    // ---- write A (normalized) ----
#pragma unroll
    for (int n = 0; n < 2 * G; ++n) {
        const int j = 8 * n + 2 * tg;
        float2 v = unpk2h(p01[n]);
        *(float2*)(AB + (size_t)(R + g) * NC + j) = make_float2(v.x * inv_lo, v.y * inv_lo);
        v = unpk2h(p23[n]);
        *(float2*)(AB + (size_t)(R + g + 8) * NC + j) = make_float2(v.x * inv_hi, v.y * inv_hi);
    }
}

// ---------------- main kernel (PDL-overlapped with prep) ----------------
__global__ __launch_bounds__(256, 2)
void cba_mma(const float* __restrict__ Qg, float* __restrict__ Outg,
             float* __restrict__ Ag)
{
    extern __shared__ char sm[];
    const int tid  = (int)threadIdx.x;
    const int lane = tid & 31;
    const int w    = tid >> 5;
    const int p    = 63 - ((int)blockIdx.x >> 4);   // heavy tiles first
    const int b    = (int)blockIdx.x & 15;
    const int c    = 2 * p + 2;
    const int G    = (c + 15) >> 4;
    const int Np   = G << 4;
    const int i0   = p << 7;
    const int g    = lane >> 2;
    const int tg   = lane & 3;
    const int R    = w << 4;
    const uint32_t smb = smem_u32(sm);

    float* OutB = Outg + (size_t)(b * NT + i0) * NE;
    float* AB   = Ag   + (size_t)(b * NT + i0) * NC;

    // ---- Q fragment LDGs first (independent of prep; overlaps the PDL wait) ----
    float2 qf[4][4];
    {
        const float* Qb = Qg + (size_t)(b * NT + i0) * NE;
#pragma unroll
        for (int k = 0; k < 4; ++k) {
            const float* q0 = Qb + (size_t)(R + g) * NE + 16 * k + 2 * tg;
            const float* q8 = q0 + 8 * NE;
            qf[k][0] = *(const float2*)q0;
            qf[k][1] = *(const float2*)q8;
            qf[k][2] = *(const float2*)(q0 + 8);
            qf[k][3] = *(const float2*)(q8 + 8);
        }
    }

    // ---- zero A tail columns [Np, 128) (independent of prep) ----
    if (G < 8) {
        const int t4 = (NC - Np) >> 2;
        for (int idx = tid; idx < 128 * t4; idx += 256) {
            const int row = idx / t4, cq = idx - row * t4;
            *(float4*)(AB + (size_t)row * NC + Np + 4 * cq) =
                make_float4(0.f, 0.f, 0.f, 0.f);
        }
    }

    // ---- wait for prep completion (no-op if PDL not configured) ----
    asm volatile("griddepcontrol.wait;" ::: "memory");

    // ---- stage K/V via cp.async from pre-converted scratch ----
    {
        const size_t boff = (size_t)b * 128 * STR;
        const char* kh = g_ksh + boff;
        const char* vh = g_vsh + boff;
        const int nchunk = c * 9;               // 16B chunks per region
        for (int idx = tid; idx < nchunk; idx += 256) {
            const uint32_t off = (uint32_t)idx * 16;
            CP16(smb + KOFF + off, kh + off);
            CP16(smb + VOFF + off, vh + off);
        }
        asm volatile("cp.async.commit_group;" ::: "memory");
        // zero pad rows [c, Np) (V pads are load-bearing for MMA2)
        const int padchunk = (Np - c) * 9;
        for (int idx = tid; idx < padchunk; idx += 256) {
            const uint32_t off = (uint32_t)(c * 9 + idx) * 16;
            *(uint4*)(sm + KOFF + off) = make_uint4(0u, 0u, 0u, 0u);
            *(uint4*)(sm + VOFF + off) = make_uint4(0u, 0u, 0u, 0u);
        }
    }

    // ---- convert Q to fp16 fragments (log2-domain prescale) ----
    uint32_t qh[4][4];
#pragma unroll
    for (int k = 0; k < 4; ++k)
#pragma unroll
        for (int t = 0; t < 4; ++t)
            qh[k][t] = pk2h(qf[k][t].x * QSCALE, qf[k][t].y * QSCALE);

    asm volatile("cp.async.wait_group 0;" ::: "memory");
    __syncthreads();

    switch (G) {
    case 1: warp_work<1>(smb, R, lane, i0, qh, OutB, AB); break;
    case 2: warp_work<2>(smb, R, lane, i0, qh, OutB, AB); break;
    case 3: warp_work<3>(smb, R, lane, i0, qh, OutB, AB); break;
    case 4: warp_work<4>(smb, R, lane, i0, qh, OutB, AB); break;
    case 5: warp_work<5>(smb, R, lane, i0, qh, OutB, AB); break;
    case 6: warp_work<6>(smb, R, lane, i0, qh, OutB, AB); break;
    case 7: warp_work<7>(smb, R, lane, i0, qh, OutB, AB); break;
    default: warp_work<8>(smb, R, lane, i0, qh, OutB, AB); break;
    }
}

extern "C" void kernel_launch(void* const* d_in, const int* in_sizes, int n_in,
                              void* d_out, int out_size)
{
    const float* Q = (const float*)d_in[0];
    const float* K = (const float*)d_in[1];
    const float* V = (const float*)d_in[2];
    float* Out = (float*)d_out;
    float* A   = Out + (size_t)NB * NT * NE;

    cba_prep<<<64, 256>>>(K, V);

    cudaFuncSetAttribute(cba_mma, cudaFuncAttributeMaxDynamicSharedMemorySize, SMEM_TOTAL);

    // PDL launch: main overlaps prep; device side waits via griddepcontrol.wait
    cudaLaunchConfig_t cfg = {};
    cfg.gridDim = dim3(1024, 1, 1);
    cfg.blockDim = dim3(256, 1, 1);
    cfg.dynamicSmemBytes = SMEM_TOTAL;
    cudaLaunchAttribute at[1];
    at[0].id = cudaLaunchAttributeProgrammaticStreamSerialization;
    at[0].val.programmaticStreamSerializationAllowed = 1;
    cfg.attrs = at;
    cfg.numAttrs = 1;
    cudaError_t e = cudaLaunchKernelEx(&cfg, cba_mma, Q, Out, A);
    if (e != cudaSuccess) {
        (void)cudaGetLastError();               // clear; fall back to plain launch
        cba_mma<<<1024, 256, SMEM_TOTAL>>>(Q, Out, A);
    }
}